// round 3
// baseline (speedup 1.0000x reference)
#include <cuda_runtime.h>
#include <cstdint>

// Problem shape (fixed by the dataset's setup_inputs):
//   word_vectors        [B, T, D]  float32
//   sent_rep_token_ids  [B, S]     int32
//   sent_rep_mask       [B, S]     int32 (bool lowered to i32 — confirmed by
//                                  the sqrt(3/4) rel_err fingerprint in R1)
//   sent_lengths        [B, S]     int32
//   sent_lengths_mask   [B, S]     int32
// Output: concat([rep_vec, mean_vec], axis=1) -> [B, 2S, D] float32,
//         followed (if out_size allows) by output_mask [B, 2S].
#define PB 16
#define PT 4096
#define PD 768
#define PS 64

// One block per (batch, sentence). 192 threads; thread i owns float4 at dim 4*i
// (192*4 == 768 exactly). Each thread streams the sentence's tokens with
// independent LDG.128s -> high MLP, fully coalesced 3 KB per token row.
__global__ __launch_bounds__(192, 8) void pool_kernel(
    const float* __restrict__ wv,
    const int* __restrict__ rep_ids,
    const int* __restrict__ rep_mask,
    const int* __restrict__ lengths,
    const int* __restrict__ len_mask,
    float* __restrict__ out,
    int write_mask_tail)
{
    const int blk = blockIdx.x;          // 0 .. B*S-1
    const int b = blk / PS;
    const int j = blk % PS;
    const int tid = threadIdx.x;         // 0 .. 191
    const int d4 = tid * 4;              // dim offset for this thread's float4

    // --- sentence span [start, end) from cumsum of lengths ---
    __shared__ int s_span[2];
    if (tid == 0) {
        int start = 0;
        const int* lrow = lengths + b * PS;
        for (int k = 0; k < j; k++) start += lrow[k];
        int end = start + lrow[j];
        if (start > PT) start = PT;      // overflow bucket dropped
        if (end   > PT) end   = PT;
        if (end < start) end = start;
        s_span[0] = start;
        s_span[1] = end;
    }
    __syncthreads();
    const int start = s_span[0];
    const int end   = s_span[1];

    const float* __restrict__ base = wv + (size_t)b * PT * PD;

    // --- segment sum + per-component nonzero count ---
    float4 sum = make_float4(0.f, 0.f, 0.f, 0.f);
    float4 cnt = make_float4(0.f, 0.f, 0.f, 0.f);
    for (int t = start; t < end; t++) {
        float4 v = *(const float4*)(base + (size_t)t * PD + d4);
        sum.x += v.x; sum.y += v.y; sum.z += v.z; sum.w += v.w;
        cnt.x += (v.x != 0.f) ? 1.f : 0.f;
        cnt.y += (v.y != 0.f) ? 1.f : 0.f;
        cnt.z += (v.z != 0.f) ? 1.f : 0.f;
        cnt.w += (v.w != 0.f) ? 1.f : 0.f;
    }

    // --- block reduce total count (empty-segment fallback detection) ---
    __shared__ float red[256];
    red[tid] = cnt.x + cnt.y + cnt.z + cnt.w;
    if (tid < 64) red[192 + tid] = 0.f;
    __syncthreads();
    for (int off = 128; off > 0; off >>= 1) {
        if (tid < off) red[tid] += red[tid + off];
        __syncthreads();
    }
    const bool empty = (red[0] == 0.f);

    const float lm = len_mask[b * PS + j] ? 1.f : 0.f;
    const float rm = rep_mask[b * PS + j] ? 1.f : 0.f;

    // --- mean vector (torch semantics: divide by per-dim nonzero count, min 1) ---
    float4 mv;
    if (empty) {
        // fallback: word_vectors[0, 0, :]
        mv = *(const float4*)(wv + d4);
    } else {
        mv.x = sum.x / ((cnt.x == 0.f) ? 1.f : cnt.x);
        mv.y = sum.y / ((cnt.y == 0.f) ? 1.f : cnt.y);
        mv.z = sum.z / ((cnt.z == 0.f) ? 1.f : cnt.z);
        mv.w = sum.w / ((cnt.w == 0.f) ? 1.f : cnt.w);
    }
    mv.x *= lm; mv.y *= lm; mv.z *= lm; mv.w *= lm;

    // --- rep vector (gather) ---
    int id = rep_ids[b * PS + j];
    if (id < 0) id = 0;
    if (id >= PT) id = PT - 1;
    float4 rv = *(const float4*)(base + (size_t)id * PD + d4);
    rv.x *= rm; rv.y *= rm; rv.z *= rm; rv.w *= rm;

    // --- write: out[b, 0:S, :] = rep, out[b, S:2S, :] = mean ---
    float* orow_rep  = out + ((size_t)b * 2 * PS + j) * PD + d4;
    float* orow_mean = out + ((size_t)b * 2 * PS + PS + j) * PD + d4;
    *(float4*)orow_rep  = rv;
    *(float4*)orow_mean = mv;

    // --- mask tail (output_mask as float), if the harness buffer includes it ---
    if (write_mask_tail && tid == 0) {
        float* mt = out + (size_t)PB * 2 * PS * PD;
        mt[b * 2 * PS + j]      = rm;
        mt[b * 2 * PS + PS + j] = lm;
    }
}

extern "C" void kernel_launch(void* const* d_in, const int* in_sizes, int n_in,
                              void* d_out, int out_size) {
    const float* wv       = (const float*)d_in[0];
    const int*   rep_ids  = (const int*)d_in[1];
    const int*   rep_mask = (const int*)d_in[2];
    const int*   lengths  = (const int*)d_in[3];
    const int*   len_mask = (const int*)d_in[4];
    float* out = (float*)d_out;

    const int vec_elems  = PB * 2 * PS * PD;   // 1,572,864
    const int mask_elems = PB * 2 * PS;        // 2,048
    int write_mask_tail = (out_size >= vec_elems + mask_elems) ? 1 : 0;

    pool_kernel<<<PB * PS, 192>>>(wv, rep_ids, rep_mask, lengths, len_mask,
                                  out, write_mask_tail);
}

// round 4
// speedup vs baseline: 1.0909x; 1.0909x over previous
#include <cuda_runtime.h>
#include <cstdint>

// Pooling_38706245271888 — GB300 sm_103a
//   word_vectors        [B, T, D]  float32
//   sent_rep_token_ids  [B, S]     int32
//   sent_rep_mask       [B, S]     int32 (bool lowered to i32)
//   sent_lengths        [B, S]     int32
//   sent_lengths_mask   [B, S]     int32
// Output: concat([rep_vec, mean_vec], axis=1) -> [B, 2S, D] float32 (+ mask tail).
#define PB 16
#define PT 4096
#define PD 768
#define PS 64

// One block per (batch, sentence). 192 threads; thread i owns float4 at dim 4*i.
// Inner loop: explicit unroll-by-4 with all 4 LDG.128s issued before any FADD
// (raises per-thread MLP; ptxas's default schedule only achieved ~2 in flight
// at the regs=40 budget). __ldcs: the 192MiB stream is read-once, keep it out
// of L2's way for the rep-token gather re-reads.
__global__ __launch_bounds__(192, 8) void pool_kernel(
    const float* __restrict__ wv,
    const int* __restrict__ rep_ids,
    const int* __restrict__ rep_mask,
    const int* __restrict__ lengths,
    const int* __restrict__ len_mask,
    float* __restrict__ out,
    int write_mask_tail)
{
    const int blk = blockIdx.x;          // 0 .. B*S-1
    const int b = blk / PS;
    const int j = blk % PS;
    const int tid = threadIdx.x;         // 0 .. 191
    const int d4 = tid * 4;

    // --- sentence span [start, end) from cumsum of lengths ---
    __shared__ int s_span[2];
    if (tid == 0) {
        int start = 0;
        const int* lrow = lengths + b * PS;
        for (int k = 0; k < j; k++) start += lrow[k];
        int end = start + lrow[j];
        if (start > PT) start = PT;      // overflow bucket dropped
        if (end   > PT) end   = PT;
        if (end < start) end = start;
        s_span[0] = start;
        s_span[1] = end;
    }
    __syncthreads();
    const int start = s_span[0];
    const int end   = s_span[1];

    const float* __restrict__ base = wv + (size_t)b * PT * PD;

    // --- segment sum + per-component nonzero count, unroll-4, loads first ---
    float4 sum = make_float4(0.f, 0.f, 0.f, 0.f);
    float4 cnt = make_float4(0.f, 0.f, 0.f, 0.f);

    const float* p = base + (size_t)start * PD + d4;
    int t = start;
    for (; t + 4 <= end; t += 4, p += 4 * PD) {
        float4 v0 = __ldcs((const float4*)(p));
        float4 v1 = __ldcs((const float4*)(p + PD));
        float4 v2 = __ldcs((const float4*)(p + 2 * PD));
        float4 v3 = __ldcs((const float4*)(p + 3 * PD));

        sum.x += v0.x; sum.y += v0.y; sum.z += v0.z; sum.w += v0.w;
        cnt.x += (v0.x != 0.f) ? 1.f : 0.f;
        cnt.y += (v0.y != 0.f) ? 1.f : 0.f;
        cnt.z += (v0.z != 0.f) ? 1.f : 0.f;
        cnt.w += (v0.w != 0.f) ? 1.f : 0.f;

        sum.x += v1.x; sum.y += v1.y; sum.z += v1.z; sum.w += v1.w;
        cnt.x += (v1.x != 0.f) ? 1.f : 0.f;
        cnt.y += (v1.y != 0.f) ? 1.f : 0.f;
        cnt.z += (v1.z != 0.f) ? 1.f : 0.f;
        cnt.w += (v1.w != 0.f) ? 1.f : 0.f;

        sum.x += v2.x; sum.y += v2.y; sum.z += v2.z; sum.w += v2.w;
        cnt.x += (v2.x != 0.f) ? 1.f : 0.f;
        cnt.y += (v2.y != 0.f) ? 1.f : 0.f;
        cnt.z += (v2.z != 0.f) ? 1.f : 0.f;
        cnt.w += (v2.w != 0.f) ? 1.f : 0.f;

        sum.x += v3.x; sum.y += v3.y; sum.z += v3.z; sum.w += v3.w;
        cnt.x += (v3.x != 0.f) ? 1.f : 0.f;
        cnt.y += (v3.y != 0.f) ? 1.f : 0.f;
        cnt.z += (v3.z != 0.f) ? 1.f : 0.f;
        cnt.w += (v3.w != 0.f) ? 1.f : 0.f;
    }
    for (; t < end; t++, p += PD) {
        float4 v = __ldcs((const float4*)(p));
        sum.x += v.x; sum.y += v.y; sum.z += v.z; sum.w += v.w;
        cnt.x += (v.x != 0.f) ? 1.f : 0.f;
        cnt.y += (v.y != 0.f) ? 1.f : 0.f;
        cnt.z += (v.z != 0.f) ? 1.f : 0.f;
        cnt.w += (v.w != 0.f) ? 1.f : 0.f;
    }

    // --- block reduce total count (empty-segment fallback detection) ---
    __shared__ float red[256];
    red[tid] = cnt.x + cnt.y + cnt.z + cnt.w;
    if (tid < 64) red[192 + tid] = 0.f;
    __syncthreads();
    for (int off = 128; off > 0; off >>= 1) {
        if (tid < off) red[tid] += red[tid + off];
        __syncthreads();
    }
    const bool empty = (red[0] == 0.f);

    const float lm = len_mask[b * PS + j] ? 1.f : 0.f;
    const float rm = rep_mask[b * PS + j] ? 1.f : 0.f;

    // --- mean vector (divide by per-dim nonzero count, min 1) ---
    float4 mv;
    if (empty) {
        mv = *(const float4*)(wv + d4);   // fallback: word_vectors[0, 0, :]
    } else {
        mv.x = sum.x / ((cnt.x == 0.f) ? 1.f : cnt.x);
        mv.y = sum.y / ((cnt.y == 0.f) ? 1.f : cnt.y);
        mv.z = sum.z / ((cnt.z == 0.f) ? 1.f : cnt.z);
        mv.w = sum.w / ((cnt.w == 0.f) ? 1.f : cnt.w);
    }
    mv.x *= lm; mv.y *= lm; mv.z *= lm; mv.w *= lm;

    // --- rep vector (gather; L2-hit likely since the stream just touched it) ---
    int id = rep_ids[b * PS + j];
    if (id < 0) id = 0;
    if (id >= PT) id = PT - 1;
    float4 rv = *(const float4*)(base + (size_t)id * PD + d4);
    rv.x *= rm; rv.y *= rm; rv.z *= rm; rv.w *= rm;

    // --- write: out[b, 0:S, :] = rep, out[b, S:2S, :] = mean ---
    float* orow_rep  = out + ((size_t)b * 2 * PS + j) * PD + d4;
    float* orow_mean = out + ((size_t)b * 2 * PS + PS + j) * PD + d4;
    *(float4*)orow_rep  = rv;
    *(float4*)orow_mean = mv;

    // --- mask tail (output_mask), if the harness buffer includes it ---
    if (write_mask_tail && tid == 0) {
        float* mt = out + (size_t)PB * 2 * PS * PD;
        mt[b * 2 * PS + j]      = rm;
        mt[b * 2 * PS + PS + j] = lm;
    }
}

extern "C" void kernel_launch(void* const* d_in, const int* in_sizes, int n_in,
                              void* d_out, int out_size) {
    const float* wv       = (const float*)d_in[0];
    const int*   rep_ids  = (const int*)d_in[1];
    const int*   rep_mask = (const int*)d_in[2];
    const int*   lengths  = (const int*)d_in[3];
    const int*   len_mask = (const int*)d_in[4];
    float* out = (float*)d_out;

    const int vec_elems  = PB * 2 * PS * PD;   // 1,572,864
    const int mask_elems = PB * 2 * PS;        // 2,048
    int write_mask_tail = (out_size >= vec_elems + mask_elems) ? 1 : 0;

    pool_kernel<<<PB * PS, 192>>>(wv, rep_ids, rep_mask, lengths, len_mask,
                                  out, write_mask_tail);
}